// round 5
// baseline (speedup 1.0000x reference)
#include <cuda_runtime.h>

// Scratch (no allocations allowed).
#define MAX_MATCH 8192
__device__ int      g_cnt    = 0;
__device__ unsigned g_ticket = 0u;
__device__ int      g_dsts[MAX_MATCH];

__device__ __forceinline__ float leaky(float v) {
    return v >= 0.f ? v : 0.2f * v;
}

// Warp-collective dot (lane reads float4 at 4*lane, stride 128 floats).
__device__ __forceinline__ float warp_dot(const float* __restrict__ row,
                                          const float* __restrict__ wvec,
                                          int D, int lane) {
    float s = 0.f;
    for (int k = 4 * lane; k < D; k += 128) {
        float4 a = *(const float4*)(row + k);
        float4 b = *(const float4*)(wvec + k);
        s += a.x * b.x + a.y * b.y + a.z * b.z + a.w * b.w;
    }
    #pragma unroll
    for (int off = 16; off > 0; off >>= 1)
        s += __shfl_down_sync(0xffffffffu, s, off);
    return s;   // valid on lane 0
}

// Single-thread dot: 32 independent float4 loads -> high MLP, one latency.
__device__ __forceinline__ float thread_dot(const float* __restrict__ row,
                                            const float* __restrict__ wvec,
                                            int D) {
    const float4* __restrict__ a = (const float4*)row;
    const float4* __restrict__ b = (const float4*)wvec;
    float acc = 0.f;
    int n4 = D >> 2;
    #pragma unroll 16
    for (int k = 0; k < n4; k++) {
        float4 x = a[k];
        float4 y = b[k];
        acc += x.x * y.x + x.y * y.y + x.z * y.z + x.w * y.w;
    }
    return acc;
}

// ---------------------------------------------------------------------------
// Fused kernel: lean edge scan in every block; last block (grid-completion
// ticket) runs the cold epilogue.
// ---------------------------------------------------------------------------
__global__ void __launch_bounds__(256)
gat_fused(const int4* __restrict__ g4, unsigned nPairs, int rem,
          const int2* __restrict__ gall,
          const float* __restrict__ h, const float* __restrict__ W,
          const float* __restrict__ bptr,
          const int* __restrict__ ip, const int* __restrict__ jp,
          int D, float* __restrict__ out) {
    const int t = threadIdx.x;
    const unsigned base = blockIdx.x * 512u + t;
    const int i = __ldg(ip);

    // ---- hot path: 2 x int4 (4 edges) per thread, coalesced ----
    int4 p0, p1;
    const bool v0 = base < nPairs;
    const bool v1 = (base + 256u) < nPairs;
    if (v0) p0 = __ldg(&g4[base]);
    if (v1) p1 = __ldg(&g4[base + 256u]);

    if (v0) {
        if (p0.x == i) { int k = atomicAdd(&g_cnt, 1); if (k < MAX_MATCH) g_dsts[k] = p0.y; }
        if (p0.z == i) { int k = atomicAdd(&g_cnt, 1); if (k < MAX_MATCH) g_dsts[k] = p0.w; }
    }
    if (v1) {
        if (p1.x == i) { int k = atomicAdd(&g_cnt, 1); if (k < MAX_MATCH) g_dsts[k] = p1.y; }
        if (p1.z == i) { int k = atomicAdd(&g_cnt, 1); if (k < MAX_MATCH) g_dsts[k] = p1.w; }
    }
    if (rem && blockIdx.x == 0 && t == 0) {
        int2 p = __ldg(&gall[(size_t)2 * nPairs]);   // trailing odd edge
        if (p.x == i) { int k = atomicAdd(&g_cnt, 1); if (k < MAX_MATCH) g_dsts[k] = p.y; }
    }

    // ---- grid-completion ticket ----
    __shared__ bool s_last;
    __syncthreads();
    if (t == 0) {
        __threadfence();   // release: list writes visible before ticket
        s_last = (atomicAdd(&g_ticket, 1u) == gridDim.x - 1u);
    }
    __syncthreads();
    if (!s_last) return;

    // ================= cold epilogue: last block only =================
    __threadfence();       // acquire: see all list writes
    int cnt = *(volatile int*)&g_cnt;
    if (cnt > MAX_MATCH) cnt = MAX_MATCH;

    const int   j    = __ldg(jp);
    const float bval = __ldg(bptr);
    const int lane = t & 31;
    const int w    = t >> 5;     // 0..7

    __shared__ float sh_ssrc, sh_sdstj, sh_warp[8];

    // warps 6/7: scalar dots, concurrent with entry loads below
    if (w == 6) {
        float s = warp_dot(h + (size_t)i * D, W, D, lane);
        if (lane == 0) sh_ssrc = s;
    } else if (w == 7) {
        float s = warp_dot(h + (size_t)j * D, W + D, D, lane);
        if (lane == 0) sh_sdstj = s;
    }

    // one thread per match entry (threads 0..191), raw dot before sync
    const bool mine = (t < 192) && (t < cnt);
    float raw = 0.f;
    if (mine) raw = thread_dot(h + (size_t)g_dsts[t] * D, W + D, D);
    __syncthreads();

    const float ssrc  = sh_ssrc;
    const float sdstj = sh_sdstj;

    float v = mine ? leaky(ssrc + raw + bval) : 0.f;
    // rare overflow: entries beyond 192, all 256 threads, stride 256
    for (int m = 192 + t; m < cnt; m += 256)
        v += leaky(ssrc + thread_dot(h + (size_t)g_dsts[m] * D, W + D, D) + bval);

    // block reduction
    #pragma unroll
    for (int off = 16; off > 0; off >>= 1)
        v += __shfl_down_sync(0xffffffffu, v, off);
    if (lane == 0) sh_warp[w] = v;
    __syncthreads();

    if (t == 0) {
        float sum = 0.f;
        #pragma unroll
        for (int k = 0; k < 8; k++) sum += sh_warp[k];
        float e = leaky(ssrc + sdstj + bval);
        out[0] = e / sum;
        // reset persistent state for the next graph replay
        g_cnt = 0;
        __threadfence();
        g_ticket = 0u;
    }
}

extern "C" void kernel_launch(void* const* d_in, const int* in_sizes, int n_in,
                              void* d_out, int out_size) {
    // metadata order: g (E*2 int32), h (N*D f32), i, j, W (2D f32), b (1 f32)
    const int*   g  = (const int*)d_in[0];
    const float* h  = (const float*)d_in[1];
    const int*   ip = (const int*)d_in[2];
    const int*   jp = (const int*)d_in[3];
    const float* W  = (const float*)d_in[4];
    const float* b  = (const float*)d_in[5];
    float* out = (float*)d_out;

    long long E = (long long)in_sizes[0] / 2;
    int D = in_sizes[4] / 2;

    unsigned nPairs = (unsigned)(E / 2);   // int4 units (2 edges each)
    int rem = (int)(E & 1);

    unsigned nBlocks = (nPairs + 511u) / 512u;
    if (nBlocks < 1u) nBlocks = 1u;

    gat_fused<<<nBlocks, 256>>>((const int4*)g, nPairs, rem, (const int2*)g,
                                h, W, b, ip, jp, D, out);
}

// round 7
// speedup vs baseline: 1.3200x; 1.3200x over previous
#include <cuda_runtime.h>

// Scratch (no allocations allowed).
#define MAX_MATCH 8192
__device__ int      g_cnt    = 0;
__device__ unsigned g_ticket = 0u;
__device__ int      g_dsts[MAX_MATCH];

__device__ __forceinline__ float leaky(float v) {
    return v >= 0.f ? v : 0.2f * v;
}

// Warp-collective dot (lane reads float4 at 4*lane, stride 128 floats).
__device__ __forceinline__ float warp_dot(const float* __restrict__ row,
                                          const float* __restrict__ wvec,
                                          int D, int lane) {
    float s = 0.f;
    for (int k = 4 * lane; k < D; k += 128) {
        float4 a = *(const float4*)(row + k);
        float4 b = *(const float4*)(wvec + k);
        s += a.x * b.x + a.y * b.y + a.z * b.z + a.w * b.w;
    }
    #pragma unroll
    for (int off = 16; off > 0; off >>= 1)
        s += __shfl_down_sync(0xffffffffu, s, off);
    return s;   // valid on lane 0
}

// Single-thread dot: 32 independent float4 loads -> one DRAM latency.
__device__ float thread_dot(const float* __restrict__ row,
                            const float* __restrict__ wvec, int D) {
    const float4* __restrict__ a = (const float4*)row;
    const float4* __restrict__ b = (const float4*)wvec;
    float acc = 0.f;
    int n4 = D >> 2;
    #pragma unroll 8
    for (int k = 0; k < n4; k++) {
        float4 x = a[k];
        float4 y = b[k];
        acc += x.x * y.x + x.y * y.y + x.z * y.z + x.w * y.w;
    }
    return acc;
}

// ---------------------------------------------------------------------------
// Persistent single-wave fused kernel: grid-stride lean scan, then last block
// (grid-completion ticket) runs the cold epilogue.
// ---------------------------------------------------------------------------
__global__ void __launch_bounds__(256, 8)
gat_fused(const int4* __restrict__ g4, unsigned nPairs, int rem,
          const int2* __restrict__ gall,
          const float* __restrict__ h, const float* __restrict__ W,
          const float* __restrict__ bptr,
          const int* __restrict__ ip, const int* __restrict__ jp,
          int D, float* __restrict__ out) {
    const int t = threadIdx.x;
    const int i = __ldg(ip);
    const unsigned stride = gridDim.x * 256u;

    // ---- hot path: grid-stride over int4 units (2 edges each) ----
    for (unsigned u = blockIdx.x * 256u + t; u < nPairs; u += stride) {
        int4 p = __ldg(&g4[u]);
        if (p.x == i) { int k = atomicAdd(&g_cnt, 1); if (k < MAX_MATCH) g_dsts[k] = p.y; }
        if (p.z == i) { int k = atomicAdd(&g_cnt, 1); if (k < MAX_MATCH) g_dsts[k] = p.w; }
    }
    if (rem && blockIdx.x == 0 && t == 0) {
        int2 p = __ldg(&gall[(size_t)2 * nPairs]);   // trailing odd edge
        if (p.x == i) { int k = atomicAdd(&g_cnt, 1); if (k < MAX_MATCH) g_dsts[k] = p.y; }
    }

    // ---- grid-completion ticket (single wave: paid once, at the end) ----
    __shared__ bool s_last;
    __syncthreads();
    if (t == 0) {
        __threadfence();   // release: list writes visible before ticket
        s_last = (atomicAdd(&g_ticket, 1u) == gridDim.x - 1u);
    }
    __syncthreads();
    if (!s_last) return;

    // ================= cold epilogue: last block only =================
    __threadfence();       // acquire: see all list writes
    int cnt = *(volatile int*)&g_cnt;
    if (cnt > MAX_MATCH) cnt = MAX_MATCH;

    const int   j    = __ldg(jp);
    const float bval = __ldg(bptr);
    const int lane = t & 31;
    const int w    = t >> 5;     // 0..7

    __shared__ float sh_ssrc, sh_sdstj, sh_warp[8];

    // warps 6/7: scalar dots, concurrent with entry loads below
    if (w == 6) {
        float s = warp_dot(h + (size_t)i * D, W, D, lane);
        if (lane == 0) sh_ssrc = s;
    } else if (w == 7) {
        float s = warp_dot(h + (size_t)j * D, W + D, D, lane);
        if (lane == 0) sh_sdstj = s;
    }

    // one thread per match entry (threads 0..191), raw dot before sync
    const bool mine = (t < 192) && (t < cnt);
    float raw = 0.f;
    if (mine) raw = thread_dot(h + (size_t)g_dsts[t] * D, W + D, D);
    __syncthreads();

    const float ssrc  = sh_ssrc;
    const float sdstj = sh_sdstj;

    float v = mine ? leaky(ssrc + raw + bval) : 0.f;
    // rare overflow: entries beyond 192
    for (int m = 192 + t; m < cnt; m += 256)
        v += leaky(ssrc + thread_dot(h + (size_t)g_dsts[m] * D, W + D, D) + bval);

    // block reduction
    #pragma unroll
    for (int off = 16; off > 0; off >>= 1)
        v += __shfl_down_sync(0xffffffffu, v, off);
    if (lane == 0) sh_warp[w] = v;
    __syncthreads();

    if (t == 0) {
        float sum = 0.f;
        #pragma unroll
        for (int k = 0; k < 8; k++) sum += sh_warp[k];
        float e = leaky(ssrc + sdstj + bval);
        out[0] = e / sum;
        // reset persistent state for the next graph replay
        g_cnt = 0;
        __threadfence();
        g_ticket = 0u;
    }
}

extern "C" void kernel_launch(void* const* d_in, const int* in_sizes, int n_in,
                              void* d_out, int out_size) {
    // metadata order: g (E*2 int32), h (N*D f32), i, j, W (2D f32), b (1 f32)
    const int*   g  = (const int*)d_in[0];
    const float* h  = (const float*)d_in[1];
    const int*   ip = (const int*)d_in[2];
    const int*   jp = (const int*)d_in[3];
    const float* W  = (const float*)d_in[4];
    const float* b  = (const float*)d_in[5];
    float* out = (float*)d_out;

    long long E = (long long)in_sizes[0] / 2;
    int D = in_sizes[4] / 2;

    unsigned nPairs = (unsigned)(E / 2);   // int4 units (2 edges each)
    int rem = (int)(E & 1);

    // Single-wave persistent grid: 148 SMs x 8 blocks of 256 = full residency.
    unsigned nBlocks = 148u * 8u;
    unsigned needed  = (nPairs + 255u) / 256u;
    if (needed < nBlocks) nBlocks = needed;
    if (nBlocks < 1u) nBlocks = 1u;

    gat_fused<<<nBlocks, 256>>>((const int4*)g, nPairs, rem, (const int2*)g,
                                h, W, b, ip, jp, D, out);
}